// round 1
// baseline (speedup 1.0000x reference)
#include <cuda_runtime.h>

#define F 128
#define N_NODES_MAX 100000

// Scratch for support = x @ W  (allocation-free rule: __device__ global)
__device__ float g_support[(size_t)N_NODES_MAX * F];

// ---------------------------------------------------------------------------
// GEMM: support[n,128] = x[n,128] @ w[128,128]
// 128 threads/block, 128 rows/block. Weight tiled in K (2 x 64x128 smem tiles,
// 32KB) + x tile 16x64 (4KB) => 36KB static smem. Each thread owns one output
// column across 16 rows at a time (16 fp32 accumulators for ILP).
// ---------------------------------------------------------------------------
__global__ void __launch_bounds__(128) gemm_kernel(const float* __restrict__ x,
                                                   const float* __restrict__ w,
                                                   int n) {
    __shared__ float ws[64 * F];   // 32 KB: K-tile of weight
    __shared__ float xs[16 * 64];  // 4 KB: 16 rows x 64 k-values

    const int t = threadIdx.x;          // 0..127 = output column
    const int row0 = blockIdx.x * 128;  // this block's row base

    for (int rg = 0; rg < 8; rg++) {    // 8 groups of 16 rows
        float acc[16];
        #pragma unroll
        for (int r = 0; r < 16; r++) acc[r] = 0.f;

        for (int kt = 0; kt < 2; kt++) {  // two 64-wide K tiles
            // load weight tile: rows [kt*64, kt*64+64) of w
            #pragma unroll
            for (int i = 0; i < 64; i++) {
                ws[i * F + t] = w[(kt * 64 + i) * F + t];
            }
            // load x tile: 16 rows x 64 cols
            for (int i = t; i < 16 * 64; i += 128) {
                int r = i >> 6;
                int k = i & 63;
                int row = row0 + rg * 16 + r;
                xs[i] = (row < n) ? x[(size_t)row * F + kt * 64 + k] : 0.f;
            }
            __syncthreads();

            #pragma unroll 8
            for (int k = 0; k < 64; k++) {
                float wv = ws[k * F + t];
                #pragma unroll
                for (int r = 0; r < 16; r++) {
                    acc[r] += xs[r * 64 + k] * wv;
                }
            }
            __syncthreads();
        }

        #pragma unroll
        for (int r = 0; r < 16; r++) {
            int row = row0 + rg * 16 + r;
            if (row < n) g_support[(size_t)row * F + t] = acc[r];
        }
    }
}

// ---------------------------------------------------------------------------
// out[i][f] = bias[f]   (d_out is poisoned; initialize before scatter)
// ---------------------------------------------------------------------------
__global__ void bias_init_kernel(const float* __restrict__ bias,
                                 float* __restrict__ out, int n) {
    // read bias once per thread (f depends only on low bits of index)
    size_t idx = (size_t)blockIdx.x * blockDim.x + threadIdx.x;
    size_t total = (size_t)n * (F / 4);  // float4 granularity
    float4* out4 = (float4*)out;
    const float4* b4 = (const float4*)bias;
    for (size_t i = idx; i < total; i += (size_t)gridDim.x * blockDim.x) {
        out4[i] = b4[i & (F / 4 - 1)];
    }
}

// ---------------------------------------------------------------------------
// Edge scatter: for each edge e (in either of the 2 edge sets):
//   out[rows[e]] += g_support[cols[e]] * vals[e]
// One warp per edge: float4 gather (512B coalesced), 4 atomicAdds/lane.
// ---------------------------------------------------------------------------
__global__ void __launch_bounds__(256) scatter_kernel(
    const float* __restrict__ vals0, const int* __restrict__ rows0,
    const int* __restrict__ cols0,
    const float* __restrict__ vals1, const int* __restrict__ rows1,
    const int* __restrict__ cols1,
    float* __restrict__ out, int E) {

    int gwarp = (blockIdx.x * blockDim.x + threadIdx.x) >> 5;
    int lane = threadIdx.x & 31;
    if (gwarp >= 2 * E) return;

    const float* vals;
    const int* rows;
    const int* cols;
    int e;
    if (gwarp < E) {
        vals = vals0; rows = rows0; cols = cols0; e = gwarp;
    } else {
        vals = vals1; rows = rows1; cols = cols1; e = gwarp - E;
    }

    float v = __ldg(&vals[e]);
    int r = __ldg(&rows[e]);
    int c = __ldg(&cols[e]);

    const float4* src = (const float4*)(g_support + (size_t)c * F);
    float4 m = src[lane];

    float* dst = out + (size_t)r * F + lane * 4;
    atomicAdd(dst + 0, m.x * v);
    atomicAdd(dst + 1, m.y * v);
    atomicAdd(dst + 2, m.z * v);
    atomicAdd(dst + 3, m.w * v);
}

// ---------------------------------------------------------------------------
// kernel_launch
// inputs (metadata order): x, weight, bias, vals0, vals1, rows0, cols0,
//                          rows1, cols1
// ---------------------------------------------------------------------------
extern "C" void kernel_launch(void* const* d_in, const int* in_sizes, int n_in,
                              void* d_out, int out_size) {
    const float* x     = (const float*)d_in[0];
    const float* w     = (const float*)d_in[1];
    const float* bias  = (const float*)d_in[2];
    const float* vals0 = (const float*)d_in[3];
    const float* vals1 = (const float*)d_in[4];
    const int* rows0   = (const int*)d_in[5];
    const int* cols0   = (const int*)d_in[6];
    const int* rows1   = (const int*)d_in[7];
    const int* cols1   = (const int*)d_in[8];
    float* out = (float*)d_out;

    int n = in_sizes[0] / F;   // 100000
    int E = in_sizes[3];       // 600000

    // 1) support = x @ W
    int gemm_blocks = (n + 127) / 128;
    gemm_kernel<<<gemm_blocks, 128>>>(x, w, n);

    // 2) out = bias (broadcast)
    bias_init_kernel<<<1184, 256>>>(bias, out, n);

    // 3) scatter both edge sets with atomics
    long long total_warps = 2LL * E;
    int sblocks = (int)((total_warps * 32 + 255) / 256);
    scatter_kernel<<<sblocks, 256>>>(vals0, rows0, cols0, vals1, rows1, cols1,
                                     out, E);
}

// round 2
// speedup vs baseline: 1.9971x; 1.9971x over previous
#include <cuda_runtime.h>
#include <mma.h>

using namespace nvcuda;

#define F 128
#define N_NODES_MAX 100000
#define N_ROWS_PAD 100224  // padded so wmma stores never go OOB (782*128 = 100096)

// Scratch for support = x @ W (allocation-free rule: __device__ global)
__device__ float g_support[(size_t)N_ROWS_PAD * F];

// ---------------------------------------------------------------------------
// GEMM: support[n,128] = x[n,128] @ w[128,128] using TF32 tensor cores with
// 3-term compensation (tf32x3) for ~fp32 accuracy.
// Block: 256 threads (8 warps), tile 128 rows x 128 cols.
// Warp grid 4(M) x 2(N): each warp computes 32x64 via 2x4 wmma m16n16k8 frags.
// K tiled 4 x 32.
// ---------------------------------------------------------------------------
__global__ void __launch_bounds__(256) gemm_tf32_kernel(
    const float* __restrict__ x, const float* __restrict__ w, int n) {
    // strides keep float4 (16B) alignment: 36*4=144B, 132*4=528B
    __shared__ float xs[128][36];   // 18.0 KB  (128 rows x 32 k)
    __shared__ float ws[32][132];   // 16.5 KB  (32 k x 128 cols)

    const int tid = threadIdx.x;
    const int wid = tid >> 5;
    const int warp_m = wid & 3;   // 0..3 -> 32-row band
    const int warp_n = wid >> 2;  // 0..1 -> 64-col band
    const int row0 = blockIdx.x * 128;

    wmma::fragment<wmma::accumulator, 16, 16, 8, float> acc[2][4];
    #pragma unroll
    for (int i = 0; i < 2; i++)
        #pragma unroll
        for (int j = 0; j < 4; j++) wmma::fill_fragment(acc[i][j], 0.0f);

    for (int kt = 0; kt < 4; kt++) {
        // load x tile: 128 x 32 (1024 float4, 4 per thread)
        #pragma unroll
        for (int i = tid; i < 1024; i += 256) {
            int r = i >> 3;       // 8 float4 per row
            int c4 = i & 7;
            int row = row0 + r;
            float4 v = make_float4(0.f, 0.f, 0.f, 0.f);
            if (row < n)
                v = *(const float4*)&x[(size_t)row * F + kt * 32 + c4 * 4];
            *(float4*)&xs[r][c4 * 4] = v;
        }
        // load w tile: 32 x 128 (1024 float4)
        #pragma unroll
        for (int i = tid; i < 1024; i += 256) {
            int r = i >> 5;       // 32 float4 per row
            int c4 = i & 31;
            *(float4*)&ws[r][c4 * 4] =
                *(const float4*)&w[(size_t)(kt * 32 + r) * F + c4 * 4];
        }
        __syncthreads();

        #pragma unroll
        for (int ks = 0; ks < 4; ks++) {  // 4 k-steps of 8
            wmma::fragment<wmma::matrix_a, 16, 16, 8, wmma::precision::tf32,
                           wmma::row_major> a_hi[2], a_lo[2];
            wmma::fragment<wmma::matrix_b, 16, 16, 8, wmma::precision::tf32,
                           wmma::row_major> b_hi[4], b_lo[4];
            #pragma unroll
            for (int i = 0; i < 2; i++) {
                wmma::load_matrix_sync(a_hi[i],
                                       &xs[warp_m * 32 + i * 16][ks * 8], 36);
                #pragma unroll
                for (int e = 0; e < a_hi[i].num_elements; e++) {
                    float f = a_hi[i].x[e];
                    float h = wmma::__float_to_tf32(f);
                    a_lo[i].x[e] = wmma::__float_to_tf32(f - h);
                    a_hi[i].x[e] = h;
                }
            }
            #pragma unroll
            for (int j = 0; j < 4; j++) {
                wmma::load_matrix_sync(b_hi[j],
                                       &ws[ks * 8][warp_n * 64 + j * 16], 132);
                #pragma unroll
                for (int e = 0; e < b_hi[j].num_elements; e++) {
                    float f = b_hi[j].x[e];
                    float h = wmma::__float_to_tf32(f);
                    b_lo[j].x[e] = wmma::__float_to_tf32(f - h);
                    b_hi[j].x[e] = h;
                }
            }
            #pragma unroll
            for (int i = 0; i < 2; i++)
                #pragma unroll
                for (int j = 0; j < 4; j++) {
                    wmma::mma_sync(acc[i][j], a_hi[i], b_hi[j], acc[i][j]);
                    wmma::mma_sync(acc[i][j], a_lo[i], b_hi[j], acc[i][j]);
                    wmma::mma_sync(acc[i][j], a_hi[i], b_lo[j], acc[i][j]);
                }
        }
        __syncthreads();
    }

    // store (g_support is row-padded, no guard needed)
    #pragma unroll
    for (int i = 0; i < 2; i++)
        #pragma unroll
        for (int j = 0; j < 4; j++) {
            size_t row = (size_t)row0 + warp_m * 32 + i * 16;
            wmma::store_matrix_sync(
                &g_support[row * F + warp_n * 64 + j * 16], acc[i][j], F,
                wmma::mem_row_major);
        }
}

// ---------------------------------------------------------------------------
// out[i][f] = bias[f]
// ---------------------------------------------------------------------------
__global__ void bias_init_kernel(const float* __restrict__ bias,
                                 float* __restrict__ out, int n) {
    size_t idx = (size_t)blockIdx.x * blockDim.x + threadIdx.x;
    size_t total = (size_t)n * (F / 4);
    float4* out4 = (float4*)out;
    const float4* b4 = (const float4*)bias;
    for (size_t i = idx; i < total; i += (size_t)gridDim.x * blockDim.x) {
        out4[i] = b4[i & (F / 4 - 1)];
    }
}

// ---------------------------------------------------------------------------
// Edge scatter: out[rows[e]] += g_support[cols[e]] * vals[e]
// Each warp owns 32 consecutive edges: coalesced index loads, shfl broadcast,
// float4 gather (512B/row), one red.global.add.v4.f32 per lane per edge.
// ---------------------------------------------------------------------------
__global__ void __launch_bounds__(256) scatter_kernel(
    const float* __restrict__ vals, const int* __restrict__ rows,
    const int* __restrict__ cols, float* __restrict__ out, int E) {
    int gw = (blockIdx.x * blockDim.x + threadIdx.x) >> 5;
    int lane = threadIdx.x & 31;
    long long base = (long long)gw * 32;
    if (base >= E) return;

    int e = (int)base + lane;
    bool valid = e < E;
    float v = valid ? __ldg(&vals[e]) : 0.f;
    int r = valid ? __ldg(&rows[e]) : 0;
    int c = valid ? __ldg(&cols[e]) : 0;

    int cnt = min(32, E - (int)base);
    const float4* sup = (const float4*)g_support;

    #pragma unroll 4
    for (int i = 0; i < cnt; i++) {
        int rr = __shfl_sync(0xffffffff, r, i);
        int cc = __shfl_sync(0xffffffff, c, i);
        float vv = __shfl_sync(0xffffffff, v, i);

        float4 m = __ldg(&sup[(size_t)cc * (F / 4) + lane]);
        float* dst = out + (size_t)rr * F + lane * 4;
        asm volatile("red.global.add.v4.f32 [%0], {%1,%2,%3,%4};"
                     :: "l"(dst), "f"(m.x * vv), "f"(m.y * vv),
                        "f"(m.z * vv), "f"(m.w * vv)
                     : "memory");
    }
}

// ---------------------------------------------------------------------------
// kernel_launch
// inputs: x, weight, bias, vals0, vals1, rows0, cols0, rows1, cols1
// ---------------------------------------------------------------------------
extern "C" void kernel_launch(void* const* d_in, const int* in_sizes, int n_in,
                              void* d_out, int out_size) {
    const float* x     = (const float*)d_in[0];
    const float* w     = (const float*)d_in[1];
    const float* bias  = (const float*)d_in[2];
    const float* vals0 = (const float*)d_in[3];
    const float* vals1 = (const float*)d_in[4];
    const int* rows0   = (const int*)d_in[5];
    const int* cols0   = (const int*)d_in[6];
    const int* rows1   = (const int*)d_in[7];
    const int* cols1   = (const int*)d_in[8];
    float* out = (float*)d_out;

    int n = in_sizes[0] / F;   // 100000
    int E = in_sizes[3];       // 600000

    // 1) support = x @ W (TF32x3 tensor cores)
    int gemm_blocks = (n + 127) / 128;
    gemm_tf32_kernel<<<gemm_blocks, 256>>>(x, w, n);

    // 2) out = bias
    bias_init_kernel<<<2048, 256>>>(bias, out, n);

    // 3) scatter both edge sets (vector reds)
    long long warps = ((long long)E + 31) / 32;
    int sblocks = (int)((warps * 32 + 255) / 256);
    scatter_kernel<<<sblocks, 256>>>(vals0, rows0, cols0, out, E);
    scatter_kernel<<<sblocks, 256>>>(vals1, rows1, cols1, out, E);
}

// round 3
// speedup vs baseline: 2.6745x; 1.3392x over previous
#include <cuda_runtime.h>
#include <cuda_bf16.h>
#include <cuda_fp16.h>
#include <mma.h>

using namespace nvcuda;

#define F 128
#define N_NODES_MAX 100000
#define N_ROWS_PAD 100224  // 782*128 = 100096 <= pad

// fp16 support (only consumer is the scatter; fp16 keeps rel_err ~1.5e-4)
__device__ __half g_support_h[(size_t)N_ROWS_PAD * F];

// ---------------------------------------------------------------------------
// GEMM: support[n,128] = x[n,128] @ w[128,128], BF16x3 compensated:
//   f = hi + lo (bf16 each);  a*b ~= a_hi*b_hi + a_hi*b_lo + a_lo*b_hi
// hi/lo split done ONCE per element into smem; mma consumes bf16 k16 frags.
// Block 256 thr (8 warps), tile 128x128, K tiled 4x32. Warp tile 32x64.
// Epilogue stages each 16x16 acc frag through smem and writes fp16.
// ---------------------------------------------------------------------------
__global__ void __launch_bounds__(256) gemm_bf16x3_kernel(
    const float* __restrict__ x, const float* __restrict__ w, int n) {
    __shared__ __nv_bfloat16 xs_hi[128][40];  // 10.0 KB
    __shared__ __nv_bfloat16 xs_lo[128][40];  // 10.0 KB
    __shared__ __nv_bfloat16 ws_hi[32][136];  // 8.5 KB
    __shared__ __nv_bfloat16 ws_lo[32][136];  // 8.5 KB

    const int tid = threadIdx.x;
    const int wid = tid >> 5;
    const int lane = tid & 31;
    const int warp_m = wid & 3;   // 32-row band
    const int warp_n = wid >> 2;  // 64-col band
    const int row0 = blockIdx.x * 128;

    wmma::fragment<wmma::accumulator, 16, 16, 16, float> acc[2][4];
    #pragma unroll
    for (int i = 0; i < 2; i++)
        #pragma unroll
        for (int j = 0; j < 4; j++) wmma::fill_fragment(acc[i][j], 0.0f);

    for (int kt = 0; kt < 4; kt++) {
        // x tile 128x32: 1024 float4, 4 per thread; split to hi/lo bf16
        #pragma unroll
        for (int i = tid; i < 1024; i += 256) {
            int r = i >> 3;
            int c = (i & 7) * 4;
            int row = row0 + r;
            float4 v = make_float4(0.f, 0.f, 0.f, 0.f);
            if (row < n)
                v = *(const float4*)&x[(size_t)row * F + kt * 32 + c];
            float f[4] = {v.x, v.y, v.z, v.w};
            #pragma unroll
            for (int q = 0; q < 4; q++) {
                __nv_bfloat16 h = __float2bfloat16_rn(f[q]);
                xs_hi[r][c + q] = h;
                xs_lo[r][c + q] = __float2bfloat16_rn(f[q] - __bfloat162float(h));
            }
        }
        // w tile 32x128
        #pragma unroll
        for (int i = tid; i < 1024; i += 256) {
            int r = i >> 5;
            int c = (i & 31) * 4;
            float4 v = *(const float4*)&w[(size_t)(kt * 32 + r) * F + c];
            float f[4] = {v.x, v.y, v.z, v.w};
            #pragma unroll
            for (int q = 0; q < 4; q++) {
                __nv_bfloat16 h = __float2bfloat16_rn(f[q]);
                ws_hi[r][c + q] = h;
                ws_lo[r][c + q] = __float2bfloat16_rn(f[q] - __bfloat162float(h));
            }
        }
        __syncthreads();

        #pragma unroll
        for (int ks = 0; ks < 2; ks++) {  // 2 k-steps of 16
            wmma::fragment<wmma::matrix_a, 16, 16, 16, __nv_bfloat16,
                           wmma::row_major> a_hi[2], a_lo[2];
            #pragma unroll
            for (int i = 0; i < 2; i++) {
                wmma::load_matrix_sync(a_hi[i],
                                       &xs_hi[warp_m * 32 + i * 16][ks * 16], 40);
                wmma::load_matrix_sync(a_lo[i],
                                       &xs_lo[warp_m * 32 + i * 16][ks * 16], 40);
            }
            #pragma unroll
            for (int j = 0; j < 4; j++) {
                wmma::fragment<wmma::matrix_b, 16, 16, 16, __nv_bfloat16,
                               wmma::row_major> b_hi, b_lo;
                wmma::load_matrix_sync(b_hi,
                                       &ws_hi[ks * 16][warp_n * 64 + j * 16], 136);
                wmma::load_matrix_sync(b_lo,
                                       &ws_lo[ks * 16][warp_n * 64 + j * 16], 136);
                #pragma unroll
                for (int i = 0; i < 2; i++) {
                    wmma::mma_sync(acc[i][j], a_hi[i], b_hi, acc[i][j]);
                    wmma::mma_sync(acc[i][j], a_hi[i], b_lo, acc[i][j]);
                    wmma::mma_sync(acc[i][j], a_lo[i], b_hi, acc[i][j]);
                }
            }
        }
        __syncthreads();
    }

    // Epilogue: stage each 16x16 frag via smem (reuse xs_hi region), write fp16.
    __syncthreads();
    float* stage = (float*)&xs_hi[0][0] + wid * 320;  // 16x20 floats per warp
    #pragma unroll
    for (int i = 0; i < 2; i++)
        #pragma unroll
        for (int j = 0; j < 4; j++) {
            wmma::store_matrix_sync(stage, acc[i][j], 20, wmma::mem_row_major);
            __syncwarp();
            int r = lane >> 1;          // 0..15
            int c = (lane & 1) * 8;     // 0 or 8
            __half hbuf[8];
            #pragma unroll
            for (int q = 0; q < 8; q++)
                hbuf[q] = __float2half_rn(stage[r * 20 + c + q]);
            size_t row = (size_t)row0 + warp_m * 32 + i * 16 + r;
            *(uint4*)&g_support_h[row * F + warp_n * 64 + j * 16 + c] =
                *(uint4*)hbuf;
            __syncwarp();
        }
}

// ---------------------------------------------------------------------------
// out[i][f] = bias[f]
// ---------------------------------------------------------------------------
__global__ void bias_init_kernel(const float* __restrict__ bias,
                                 float* __restrict__ out, int n) {
    size_t idx = (size_t)blockIdx.x * blockDim.x + threadIdx.x;
    size_t total = (size_t)n * (F / 4);
    float4* out4 = (float4*)out;
    const float4* b4 = (const float4*)bias;
    for (size_t i = idx; i < total; i += (size_t)gridDim.x * blockDim.x) {
        out4[i] = b4[i & (F / 4 - 1)];
    }
}

// ---------------------------------------------------------------------------
// Edge scatter (both edge sets in one launch):
//   out[rows[e]] += support_h[cols[e]] * vals[e]
// Warp owns 32 edges: coalesced index loads + shfl broadcast.
// Gather: 8B (4 fp16) per lane (256B/row). One red.global.add.v4.f32 per lane.
// ---------------------------------------------------------------------------
__global__ void __launch_bounds__(256) scatter_kernel(
    const float* __restrict__ vals0, const int* __restrict__ rows0,
    const int* __restrict__ cols0,
    const float* __restrict__ vals1, const int* __restrict__ rows1,
    const int* __restrict__ cols1,
    float* __restrict__ out, int E) {
    int gw = (blockIdx.x * blockDim.x + threadIdx.x) >> 5;
    int lane = threadIdx.x & 31;
    int warps_per_set = (E + 31) >> 5;
    if (gw >= 2 * warps_per_set) return;

    const float* vals;
    const int* rows;
    const int* cols;
    int wset = gw;
    if (gw < warps_per_set) {
        vals = vals0; rows = rows0; cols = cols0;
    } else {
        vals = vals1; rows = rows1; cols = cols1; wset = gw - warps_per_set;
    }
    int base = wset * 32;

    int e = base + lane;
    bool valid = e < E;
    float v = valid ? __ldg(&vals[e]) : 0.f;
    int r = valid ? __ldg(&rows[e]) : 0;
    int c = valid ? __ldg(&cols[e]) : 0;

    int cnt = min(32, E - base);
    const uint2* sup = (const uint2*)g_support_h;  // 4 fp16 per uint2

    #pragma unroll 4
    for (int i = 0; i < cnt; i++) {
        int rr = __shfl_sync(0xffffffff, r, i);
        int cc = __shfl_sync(0xffffffff, c, i);
        float vv = __shfl_sync(0xffffffff, v, i);

        uint2 packed = __ldg(&sup[(size_t)cc * (F / 4) + lane]);
        __half2 h01 = *(__half2*)&packed.x;
        __half2 h23 = *(__half2*)&packed.y;
        float2 f01 = __half22float2(h01);
        float2 f23 = __half22float2(h23);

        float* dst = out + (size_t)rr * F + lane * 4;
        asm volatile("red.global.add.v4.f32 [%0], {%1,%2,%3,%4};"
                     :: "l"(dst), "f"(f01.x * vv), "f"(f01.y * vv),
                        "f"(f23.x * vv), "f"(f23.y * vv)
                     : "memory");
    }
}

// ---------------------------------------------------------------------------
// kernel_launch
// inputs: x, weight, bias, vals0, vals1, rows0, cols0, rows1, cols1
// ---------------------------------------------------------------------------
extern "C" void kernel_launch(void* const* d_in, const int* in_sizes, int n_in,
                              void* d_out, int out_size) {
    const float* x     = (const float*)d_in[0];
    const float* w     = (const float*)d_in[1];
    const float* bias  = (const float*)d_in[2];
    const float* vals0 = (const float*)d_in[3];
    const float* vals1 = (const float*)d_in[4];
    const int* rows0   = (const int*)d_in[5];
    const int* cols0   = (const int*)d_in[6];
    const int* rows1   = (const int*)d_in[7];
    const int* cols1   = (const int*)d_in[8];
    float* out = (float*)d_out;

    int n = in_sizes[0] / F;   // 100000
    int E = in_sizes[3];       // 600000

    // 1) support_h = fp16(x @ W) via BF16x3 tensor cores
    int gemm_blocks = (n + 127) / 128;
    gemm_bf16x3_kernel<<<gemm_blocks, 256>>>(x, w, n);

    // 2) out = bias
    bias_init_kernel<<<2048, 256>>>(bias, out, n);

    // 3) scatter both edge sets (one launch, vector reds)
    long long total_warps = 2LL * ((E + 31) / 32);
    int sblocks = (int)((total_warps * 32 + 255) / 256);
    scatter_kernel<<<sblocks, 256>>>(vals0, rows0, cols0, vals1, rows1, cols1,
                                     out, E);
}